// round 16
// baseline (speedup 1.0000x reference)
#include <cuda_runtime.h>
#include <cuda_bf16.h>
#include <cstdint>

#define VOCAB 50257
#define EMB   16
#define BS    8
#define MCW   512
#define NROW  (BS * MCW)   // 4096
#define NCHUNK 8           // attnout p-chunks
#define CHUNK  (MCW / NCHUNK)  // 64
typedef unsigned long long ull;

// ---------------- scratch (static device globals; no allocs) ----------------
__device__ float g_q[NROW * EMB];
__device__ float g_k[NROW * EMB];
__device__ float g_v[NROW * EMB];
__device__ float g_sc[BS * MCW * MCW];          // TRANSPOSED probs: [b][k][q] (8 MB)
__device__ float g_part[NCHUNK * EMB * NROW];   // attnout partials: [chunk][e][r]
__device__ float g_out_t[EMB * NROW];           // collapsed attnout: [e][r]

__device__ __forceinline__ ull pack2(float lo, float hi) {
    ull r;
    asm("mov.b64 %0, {%1, %2};" : "=l"(r) : "f"(lo), "f"(hi));
    return r;
}
__device__ __forceinline__ void unpack2(ull p, float& lo, float& hi) {
    asm("mov.b64 {%0, %1}, %2;" : "=f"(lo), "=f"(hi) : "l"(p));
}

// ---------------- Kernel A: embeddings -> Q, K, V ----------------
__global__ void qkv_kernel(const int* __restrict__ x,
                           const float* __restrict__ emb_table,
                           const float* __restrict__ Wq, const float* __restrict__ bq,
                           const float* __restrict__ Wk, const float* __restrict__ bk,
                           const float* __restrict__ Wv, const float* __restrict__ bv) {
    __shared__ float sWq[EMB * EMB], sWk[EMB * EMB], sWv[EMB * EMB];
    __shared__ float sbq[EMB], sbk[EMB], sbv[EMB];
    int tid = threadIdx.x;
    if (tid < EMB * EMB) { sWq[tid] = Wq[tid]; sWk[tid] = Wk[tid]; sWv[tid] = Wv[tid]; }
    if (tid < EMB)       { sbq[tid] = bq[tid]; sbk[tid] = bk[tid]; sbv[tid] = bv[tid]; }
    __syncthreads();

    int t = blockIdx.x * blockDim.x + tid;
    if (t >= NROW) return;
    int tok = x[t];

    float emb[EMB];
    const float4* ep = reinterpret_cast<const float4*>(emb_table + (size_t)tok * EMB);
#pragma unroll
    for (int i = 0; i < 4; i++) {
        float4 v4 = ep[i];
        emb[4 * i + 0] = v4.x; emb[4 * i + 1] = v4.y;
        emb[4 * i + 2] = v4.z; emb[4 * i + 3] = v4.w;
    }

#pragma unroll
    for (int i = 0; i < EMB; i++) {
        float aq = sbq[i], ak = sbk[i], av = sbv[i];
#pragma unroll
        for (int e = 0; e < EMB; e++) {
            aq += emb[e] * sWq[i * EMB + e];
            ak += emb[e] * sWk[i * EMB + e];
            av += emb[e] * sWv[i * EMB + e];
        }
        g_q[t * EMB + i] = aq;
        g_k[t * EMB + i] = ak;
        g_v[t * EMB + i] = av;
    }
}

// ---------------- Kernel B: fused scores + mask + zero->-inf + softmax(q) ----------------
#define QPAD 20
__global__ __launch_bounds__(256) void scorexmax_kernel() {
    __shared__ float sQ[MCW * QPAD];   // [q][20] padded, 40 KB
    int b = blockIdx.y;
    int kbase = blockIdx.x * 8;
    int tid = threadIdx.x;
    int warp = tid >> 5, lane = tid & 31;

    for (int i = tid; i < MCW * 4; i += 256) {
        int q = i >> 2, e4 = i & 3;
        float4 v4 = *reinterpret_cast<const float4*>(g_q + ((size_t)(b * MCW + q)) * EMB + e4 * 4);
        *reinterpret_cast<float4*>(sQ + q * QPAD + e4 * 4) = v4;
    }
    __syncthreads();

    int k = kbase + warp;
    float krow[EMB];
    const float4* kp = reinterpret_cast<const float4*>(g_k + ((size_t)(b * MCW + k)) * EMB);
#pragma unroll
    for (int i = 0; i < 4; i++) {
        float4 v4 = kp[i];
        krow[4 * i + 0] = v4.x; krow[4 * i + 1] = v4.y;
        krow[4 * i + 2] = v4.z; krow[4 * i + 3] = v4.w;
    }

    float* prow = g_sc + (size_t)b * MCW * MCW + (size_t)k * MCW;
    const float NEG_INF = __int_as_float(0xff800000);

    float v[16];
    bool live[16];
#pragma unroll
    for (int j = 0; j < 16; j++) {
        int q = j * 32 + lane;
        if (j * 32 + 31 < k) {            // chunk entirely masked: prob = 0 exactly
            live[j] = false;
            v[j] = NEG_INF;
            prow[q] = 0.0f;
        } else {
            live[j] = true;
            float dot = 0.f;
#pragma unroll
            for (int e4 = 0; e4 < 4; e4++) {
                float4 a = *reinterpret_cast<const float4*>(sQ + q * QPAD + e4 * 4);
                dot += a.x * krow[4 * e4 + 0] + a.y * krow[4 * e4 + 1]
                     + a.z * krow[4 * e4 + 2] + a.w * krow[4 * e4 + 3];
            }
            float val = (q >= k) ? dot : 0.0f;
            if (val == 0.0f) val = NEG_INF;
            v[j] = val;
        }
    }

    float mx = NEG_INF;
#pragma unroll
    for (int j = 0; j < 16; j++) mx = fmaxf(mx, v[j]);
#pragma unroll
    for (int s = 16; s > 0; s >>= 1) mx = fmaxf(mx, __shfl_xor_sync(0xffffffffu, mx, s));

    float sum = 0.f;
#pragma unroll
    for (int j = 0; j < 16; j++) {
        if (live[j]) { v[j] = expf(v[j] - mx); sum += v[j]; }
    }
#pragma unroll
    for (int s = 16; s > 0; s >>= 1) sum += __shfl_xor_sync(0xffffffffu, sum, s);

    float inv = 1.0f / sum;
#pragma unroll
    for (int j = 0; j < 16; j++) {
        if (live[j]) prow[j * 32 + lane] = v[j] * inv;
    }
}

// ---------------- Kernel C: attnout partials, 8 p-chunks, triangular skip ----------------
__global__ void attnout_kernel() {
    int b = blockIdx.y;
    int w0 = blockIdx.x * 32;
    int c  = blockIdx.z;
    int wl = threadIdx.x, pg = threadIdx.y;

    if (c * CHUNK > w0 + 31) {           // prob exactly 0 here: write zeros, done
        if (pg == 0) {
#pragma unroll
            for (int e = 0; e < EMB; e++)
                g_part[(size_t)c * EMB * NROW + (size_t)e * NROW + b * MCW + w0 + wl] = 0.f;
        }
        return;
    }

    __shared__ float sV[CHUNK * EMB];    // 4 KB
    __shared__ float red[256 * EMB];     // 16 KB
    int tid = pg * 32 + wl;

    for (int i = tid; i < CHUNK * EMB; i += 256)
        sV[i] = g_v[(size_t)b * MCW * EMB + c * CHUNK * EMB + i];
    __syncthreads();

    float acc[EMB];
#pragma unroll
    for (int e = 0; e < EMB; e++) acc[e] = 0.f;

    const float* wbase = g_sc + (size_t)b * MCW * MCW + w0 + wl;
#pragma unroll
    for (int pi = 0; pi < CHUNK / 8; pi++) {
        int pl = pi * 8 + pg;
        float wgt = wbase[(size_t)(c * CHUNK + pl) * MCW];
#pragma unroll
        for (int e = 0; e < EMB; e++) acc[e] += wgt * sV[pl * EMB + e];
    }

#pragma unroll
    for (int e = 0; e < EMB; e++) red[tid * EMB + e] = acc[e];
    __syncthreads();

    if (pg == 0) {
#pragma unroll
        for (int e = 0; e < EMB; e++) {
            float s = 0.f;
#pragma unroll
            for (int g = 0; g < 8; g++) s += red[(g * 32 + wl) * EMB + e];
            g_part[(size_t)c * EMB * NROW + (size_t)e * NROW + b * MCW + w0 + wl] = s;
        }
    }
}

// ---------------- Kernel C2: collapse 8 partial planes -> g_out_t ----------------
__global__ __launch_bounds__(256) void collapse_kernel() {
    int i = blockIdx.x * 256 + threadIdx.x;       // float4 index
    const float4* p = reinterpret_cast<const float4*>(g_part);
    float4 a = p[i];
#pragma unroll
    for (int c = 1; c < NCHUNK; c++) {
        float4 b = p[c * (EMB * NROW / 4) + i];
        a.x += b.x; a.y += b.y; a.z += b.z; a.w += b.w;
    }
    reinterpret_cast<float4*>(g_out_t)[i] = a;
}

// ---------------- Kernel D: logits = out @ Wl.T + bl  (823 MB write) ----------------
// Column-pair k=4 (R14 structure) with a ROW-DUPLICATED shared tile:
// s2[e][2r] = s2[e][2r+1] = out[r][e], so the inner loop reads (val,val) f32x2
// operands straight from shared (2x LDS.128 per e) — eliminating the 128
// splat MOVs per iteration that were ~35-40us of issue-port time in R14.
#define E_RT 64
__global__ __launch_bounds__(128, 4) void logits_kernel(const float* __restrict__ Wl,
                                                        const float* __restrict__ bl,
                                                        float* __restrict__ out) {
    __shared__ __align__(16) float s2[EMB * E_RT * 2];   // duplicated tile, 8 KB
    int tid = threadIdx.x;
    int rbase = blockIdx.y * E_RT;

    // stage duplicated tile from collapsed plane:
    // 2 source float4 per thread -> 4 duplicated float4 stores
#pragma unroll
    for (int j = 0; j < 2; j++) {
        int i4 = j * 128 + tid;              // source float4 index (256 total)
        int e = i4 >> 4, rl4 = i4 & 15;      // 16 source float4 per e-row
        float4 v4 = *reinterpret_cast<const float4*>(g_out_t + e * NROW + rbase + rl4 * 4);
        float* dst = s2 + e * (2 * E_RT) + rl4 * 8;
        *reinterpret_cast<float4*>(dst)     = make_float4(v4.x, v4.x, v4.y, v4.y);
        *reinterpret_cast<float4*>(dst + 4) = make_float4(v4.z, v4.z, v4.w, v4.w);
    }

    int v0 = blockIdx.x * 512 + tid;     // pair A lo
    int v1 = v0 + 128;                   // pair A hi
    int v2 = v0 + 256;                   // pair B lo
    int v3 = v0 + 384;                   // pair B hi
    bool ok0 = (v0 < VOCAB), ok1 = (v1 < VOCAB), ok2 = (v2 < VOCAB), ok3 = (v3 < VOCAB);

    ull wA[EMB], wB[EMB], bA, bB;
    {
        float wl0[EMB], wl1[EMB], wl2[EMB], wl3[EMB];
#pragma unroll
        for (int i = 0; i < 4; i++) {
            float4 q0 = ok0 ? reinterpret_cast<const float4*>(Wl + (size_t)v0 * EMB)[i]
                            : make_float4(0.f, 0.f, 0.f, 0.f);
            float4 q1 = ok1 ? reinterpret_cast<const float4*>(Wl + (size_t)v1 * EMB)[i]
                            : make_float4(0.f, 0.f, 0.f, 0.f);
            float4 q2 = ok2 ? reinterpret_cast<const float4*>(Wl + (size_t)v2 * EMB)[i]
                            : make_float4(0.f, 0.f, 0.f, 0.f);
            float4 q3 = ok3 ? reinterpret_cast<const float4*>(Wl + (size_t)v3 * EMB)[i]
                            : make_float4(0.f, 0.f, 0.f, 0.f);
            wl0[4*i+0]=q0.x; wl0[4*i+1]=q0.y; wl0[4*i+2]=q0.z; wl0[4*i+3]=q0.w;
            wl1[4*i+0]=q1.x; wl1[4*i+1]=q1.y; wl1[4*i+2]=q1.z; wl1[4*i+3]=q1.w;
            wl2[4*i+0]=q2.x; wl2[4*i+1]=q2.y; wl2[4*i+2]=q2.z; wl2[4*i+3]=q2.w;
            wl3[4*i+0]=q3.x; wl3[4*i+1]=q3.y; wl3[4*i+2]=q3.z; wl3[4*i+3]=q3.w;
        }
#pragma unroll
        for (int e = 0; e < EMB; e++) {
            wA[e] = pack2(wl0[e], wl1[e]);
            wB[e] = pack2(wl2[e], wl3[e]);
        }
        bA = pack2(ok0 ? bl[v0] : 0.f, ok1 ? bl[v1] : 0.f);
        bB = pack2(ok2 ? bl[v2] : 0.f, ok3 ? bl[v3] : 0.f);
    }
    __syncthreads();

#pragma unroll 1
    for (int rpp = 0; rpp < E_RT / 4; rpp++) {      // 4 rows per iteration
        ull a0 = bA, a1 = bA, a2 = bA, a3 = bA;     // pair A, rows 0..3
        ull c0 = bB, c1 = bB, c2 = bB, c3 = bB;     // pair B, rows 0..3
#pragma unroll
        for (int e = 0; e < EMB; e++) {
            const float* src = s2 + e * (2 * E_RT) + rpp * 8;
            ulonglong2 q0 = *reinterpret_cast<const ulonglong2*>(src);      // (r0r0, r1r1)
            ulonglong2 q1 = *reinterpret_cast<const ulonglong2*>(src + 4);  // (r2r2, r3r3)
            asm("fma.rn.f32x2 %0, %1, %2, %0;" : "+l"(a0) : "l"(q0.x), "l"(wA[e]));
            asm("fma.rn.f32x2 %0, %1, %2, %0;" : "+l"(c0) : "l"(q0.x), "l"(wB[e]));
            asm("fma.rn.f32x2 %0, %1, %2, %0;" : "+l"(a1) : "l"(q0.y), "l"(wA[e]));
            asm("fma.rn.f32x2 %0, %1, %2, %0;" : "+l"(c1) : "l"(q0.y), "l"(wB[e]));
            asm("fma.rn.f32x2 %0, %1, %2, %0;" : "+l"(a2) : "l"(q1.x), "l"(wA[e]));
            asm("fma.rn.f32x2 %0, %1, %2, %0;" : "+l"(c2) : "l"(q1.x), "l"(wB[e]));
            asm("fma.rn.f32x2 %0, %1, %2, %0;" : "+l"(a3) : "l"(q1.y), "l"(wA[e]));
            asm("fma.rn.f32x2 %0, %1, %2, %0;" : "+l"(c3) : "l"(q1.y), "l"(wB[e]));
        }
        size_t r = (size_t)(rbase + 4 * rpp);
        float lo, hi;
        ull accA[4] = {a0, a1, a2, a3};
        ull accB[4] = {c0, c1, c2, c3};
#pragma unroll
        for (int i = 0; i < 4; i++) {
            float* orow = out + (r + i) * VOCAB;
            unpack2(accA[i], lo, hi);
            if (ok0) __stcs(orow + v0, lo);
            if (ok1) __stcs(orow + v1, hi);
            unpack2(accB[i], lo, hi);
            if (ok2) __stcs(orow + v2, lo);
            if (ok3) __stcs(orow + v3, hi);
        }
    }
}

// ---------------- launch ----------------
extern "C" void kernel_launch(void* const* d_in, const int* in_sizes, int n_in,
                              void* d_out, int out_size) {
    const int*   x   = (const int*)  d_in[0];
    const float* emb = (const float*)d_in[1];
    const float* Wq  = (const float*)d_in[2];
    const float* bq  = (const float*)d_in[3];
    const float* Wk  = (const float*)d_in[4];
    const float* bk  = (const float*)d_in[5];
    const float* Wv  = (const float*)d_in[6];
    const float* bv  = (const float*)d_in[7];
    const float* Wl  = (const float*)d_in[8];
    const float* bl  = (const float*)d_in[9];
    float* out = (float*)d_out;

    qkv_kernel<<<NROW / 256, 256>>>(x, emb, Wq, bq, Wk, bk, Wv, bv);

    dim3 gB(MCW / 8, BS);
    scorexmax_kernel<<<gB, 256>>>();

    dim3 gD(MCW / 32, BS, NCHUNK), bD(32, 8);
    attnout_kernel<<<gD, bD>>>();

    collapse_kernel<<<EMB * NROW / 4 / 256, 256>>>();

    dim3 gE((VOCAB + 511) / 512, NROW / E_RT);
    logits_kernel<<<gE, 128>>>(Wl, bl, out);
}

// round 17
// speedup vs baseline: 1.0870x; 1.0870x over previous
#include <cuda_runtime.h>
#include <cuda_bf16.h>
#include <cstdint>

#define VOCAB 50257
#define EMB   16
#define BS    8
#define MCW   512
#define NROW  (BS * MCW)   // 4096
#define NCHUNK 8           // attnout p-chunks
#define CHUNK  (MCW / NCHUNK)  // 64
typedef unsigned long long ull;

// ---------------- scratch (static device globals; no allocs) ----------------
__device__ float g_q[NROW * EMB];
__device__ float g_k[NROW * EMB];
__device__ float g_v[NROW * EMB];
__device__ float g_sc[BS * MCW * MCW];   // TRANSPOSED probs: [b][k][q] (8 MB)
__device__ float g_out_t[EMB * NROW];    // attnout accumulator: [e][r] (atomic)

__device__ __forceinline__ ull pack2(float lo, float hi) {
    ull r;
    asm("mov.b64 %0, {%1, %2};" : "=l"(r) : "f"(lo), "f"(hi));
    return r;
}
__device__ __forceinline__ void unpack2(ull p, float& lo, float& hi) {
    asm("mov.b64 {%0, %1}, %2;" : "=f"(lo), "=f"(hi) : "l"(p));
}

// ---------------- Kernel A: embeddings -> Q, K, V (+ zero g_out_t) ----------------
__global__ void qkv_kernel(const int* __restrict__ x,
                           const float* __restrict__ emb_table,
                           const float* __restrict__ Wq, const float* __restrict__ bq,
                           const float* __restrict__ Wk, const float* __restrict__ bk,
                           const float* __restrict__ Wv, const float* __restrict__ bv) {
    __shared__ float sWq[EMB * EMB], sWk[EMB * EMB], sWv[EMB * EMB];
    __shared__ float sbq[EMB], sbk[EMB], sbv[EMB];
    int tid = threadIdx.x;
    int t = blockIdx.x * blockDim.x + tid;

    // zero the attnout accumulator (re-zeroed every launch: graph-replay safe)
    {
        float4* po = reinterpret_cast<float4*>(g_out_t);
#pragma unroll
        for (int j = 0; j < 4; j++)
            po[t + j * NROW] = make_float4(0.f, 0.f, 0.f, 0.f);
    }

    if (tid < EMB * EMB) { sWq[tid] = Wq[tid]; sWk[tid] = Wk[tid]; sWv[tid] = Wv[tid]; }
    if (tid < EMB)       { sbq[tid] = bq[tid]; sbk[tid] = bk[tid]; sbv[tid] = bv[tid]; }
    __syncthreads();

    if (t >= NROW) return;
    int tok = x[t];

    float emb[EMB];
    const float4* ep = reinterpret_cast<const float4*>(emb_table + (size_t)tok * EMB);
#pragma unroll
    for (int i = 0; i < 4; i++) {
        float4 v4 = ep[i];
        emb[4 * i + 0] = v4.x; emb[4 * i + 1] = v4.y;
        emb[4 * i + 2] = v4.z; emb[4 * i + 3] = v4.w;
    }

#pragma unroll
    for (int i = 0; i < EMB; i++) {
        float aq = sbq[i], ak = sbk[i], av = sbv[i];
#pragma unroll
        for (int e = 0; e < EMB; e++) {
            aq += emb[e] * sWq[i * EMB + e];
            ak += emb[e] * sWk[i * EMB + e];
            av += emb[e] * sWv[i * EMB + e];
        }
        g_q[t * EMB + i] = aq;
        g_k[t * EMB + i] = ak;
        g_v[t * EMB + i] = av;
    }
}

// ---------------- Kernel B: fused scores + mask + zero->-inf + softmax(q) ----------------
#define QPAD 20
__global__ __launch_bounds__(256) void scorexmax_kernel() {
    __shared__ float sQ[MCW * QPAD];   // [q][20] padded, 40 KB
    int b = blockIdx.y;
    int kbase = blockIdx.x * 8;
    int tid = threadIdx.x;
    int warp = tid >> 5, lane = tid & 31;

    for (int i = tid; i < MCW * 4; i += 256) {
        int q = i >> 2, e4 = i & 3;
        float4 v4 = *reinterpret_cast<const float4*>(g_q + ((size_t)(b * MCW + q)) * EMB + e4 * 4);
        *reinterpret_cast<float4*>(sQ + q * QPAD + e4 * 4) = v4;
    }
    __syncthreads();

    int k = kbase + warp;
    float krow[EMB];
    const float4* kp = reinterpret_cast<const float4*>(g_k + ((size_t)(b * MCW + k)) * EMB);
#pragma unroll
    for (int i = 0; i < 4; i++) {
        float4 v4 = kp[i];
        krow[4 * i + 0] = v4.x; krow[4 * i + 1] = v4.y;
        krow[4 * i + 2] = v4.z; krow[4 * i + 3] = v4.w;
    }

    float* prow = g_sc + (size_t)b * MCW * MCW + (size_t)k * MCW;
    const float NEG_INF = __int_as_float(0xff800000);

    float v[16];
    bool live[16];
#pragma unroll
    for (int j = 0; j < 16; j++) {
        int q = j * 32 + lane;
        if (j * 32 + 31 < k) {            // chunk entirely masked: prob = 0 exactly
            live[j] = false;
            v[j] = NEG_INF;
            prow[q] = 0.0f;
        } else {
            live[j] = true;
            float dot = 0.f;
#pragma unroll
            for (int e4 = 0; e4 < 4; e4++) {
                float4 a = *reinterpret_cast<const float4*>(sQ + q * QPAD + e4 * 4);
                dot += a.x * krow[4 * e4 + 0] + a.y * krow[4 * e4 + 1]
                     + a.z * krow[4 * e4 + 2] + a.w * krow[4 * e4 + 3];
            }
            float val = (q >= k) ? dot : 0.0f;
            if (val == 0.0f) val = NEG_INF;
            v[j] = val;
        }
    }

    float mx = NEG_INF;
#pragma unroll
    for (int j = 0; j < 16; j++) mx = fmaxf(mx, v[j]);
#pragma unroll
    for (int s = 16; s > 0; s >>= 1) mx = fmaxf(mx, __shfl_xor_sync(0xffffffffu, mx, s));

    float sum = 0.f;
#pragma unroll
    for (int j = 0; j < 16; j++) {
        if (live[j]) { v[j] = expf(v[j] - mx); sum += v[j]; }
    }
#pragma unroll
    for (int s = 16; s > 0; s >>= 1) sum += __shfl_xor_sync(0xffffffffu, sum, s);

    float inv = 1.0f / sum;
#pragma unroll
    for (int j = 0; j < 16; j++) {
        if (live[j]) prow[j * 32 + lane] = v[j] * inv;
    }
}

// ---------------- Kernel C: attnout, 8 p-chunks, atomic accumulate ----------------
// grid (16 w-tiles, 8 b, 8 chunks), block (32, 8). Fully-masked chunks exit.
// Partial sums go straight into g_out_t via atomicAdd (g_out_t zeroed in qkv).
__global__ void attnout_kernel() {
    int b = blockIdx.y;
    int w0 = blockIdx.x * 32;
    int c  = blockIdx.z;
    if (c * CHUNK > w0 + 31) return;     // prob exactly 0 here: contributes nothing

    __shared__ float sV[CHUNK * EMB];    // 4 KB
    __shared__ float red[256 * EMB];     // 16 KB
    int wl = threadIdx.x, pg = threadIdx.y;
    int tid = pg * 32 + wl;

    for (int i = tid; i < CHUNK * EMB; i += 256)
        sV[i] = g_v[(size_t)b * MCW * EMB + c * CHUNK * EMB + i];
    __syncthreads();

    float acc[EMB];
#pragma unroll
    for (int e = 0; e < EMB; e++) acc[e] = 0.f;

    const float* wbase = g_sc + (size_t)b * MCW * MCW + w0 + wl;
#pragma unroll
    for (int pi = 0; pi < CHUNK / 8; pi++) {
        int pl = pi * 8 + pg;
        float wgt = wbase[(size_t)(c * CHUNK + pl) * MCW];
#pragma unroll
        for (int e = 0; e < EMB; e++) acc[e] += wgt * sV[pl * EMB + e];
    }

#pragma unroll
    for (int e = 0; e < EMB; e++) red[tid * EMB + e] = acc[e];
    __syncthreads();

    if (pg == 0) {
#pragma unroll
        for (int e = 0; e < EMB; e++) {
            float s = 0.f;
#pragma unroll
            for (int g = 0; g < 8; g++) s += red[(g * 32 + wl) * EMB + e];
            atomicAdd(&g_out_t[(size_t)e * NROW + b * MCW + w0 + wl], s);
        }
    }
}

// ---------------- Kernel D: logits = out @ Wl.T + bl  (823 MB write) ----------------
// R14 champion structure, byte-exact: column-pair k=4, E_RT=64, 1 LDS per
// output (R16 proved the splat MOVs are cheaper than extra LDS traffic).
#define E_RT 64
__global__ __launch_bounds__(128, 4) void logits_kernel(const float* __restrict__ Wl,
                                                        const float* __restrict__ bl,
                                                        float* __restrict__ out) {
    __shared__ __align__(16) float s[EMB * E_RT];   // s[e][r_local], 4 KB
    int tid = threadIdx.x;
    int rbase = blockIdx.y * E_RT;

    // stage s tile from accumulator plane: 2x LDG.128 / STS.128 per thread
#pragma unroll
    for (int j = 0; j < 2; j++) {
        int i4 = j * 128 + tid;              // float4 index within tile (256 total)
        int e = i4 >> 4, rl4 = i4 & 15;      // E_RT/4 = 16 float4 per row
        float4 v4 = *reinterpret_cast<const float4*>(g_out_t + e * NROW + rbase + rl4 * 4);
        *reinterpret_cast<float4*>(s + e * E_RT + rl4 * 4) = v4;
    }

    int v0 = blockIdx.x * 512 + tid;     // pair A lo
    int v1 = v0 + 128;                   // pair A hi
    int v2 = v0 + 256;                   // pair B lo
    int v3 = v0 + 384;                   // pair B hi
    bool ok0 = (v0 < VOCAB), ok1 = (v1 < VOCAB), ok2 = (v2 < VOCAB), ok3 = (v3 < VOCAB);

    ull wA[EMB], wB[EMB], bA, bB;
    {
        float wl0[EMB], wl1[EMB], wl2[EMB], wl3[EMB];
#pragma unroll
        for (int i = 0; i < 4; i++) {
            float4 q0 = ok0 ? reinterpret_cast<const float4*>(Wl + (size_t)v0 * EMB)[i]
                            : make_float4(0.f, 0.f, 0.f, 0.f);
            float4 q1 = ok1 ? reinterpret_cast<const float4*>(Wl + (size_t)v1 * EMB)[i]
                            : make_float4(0.f, 0.f, 0.f, 0.f);
            float4 q2 = ok2 ? reinterpret_cast<const float4*>(Wl + (size_t)v2 * EMB)[i]
                            : make_float4(0.f, 0.f, 0.f, 0.f);
            float4 q3 = ok3 ? reinterpret_cast<const float4*>(Wl + (size_t)v3 * EMB)[i]
                            : make_float4(0.f, 0.f, 0.f, 0.f);
            wl0[4*i+0]=q0.x; wl0[4*i+1]=q0.y; wl0[4*i+2]=q0.z; wl0[4*i+3]=q0.w;
            wl1[4*i+0]=q1.x; wl1[4*i+1]=q1.y; wl1[4*i+2]=q1.z; wl1[4*i+3]=q1.w;
            wl2[4*i+0]=q2.x; wl2[4*i+1]=q2.y; wl2[4*i+2]=q2.z; wl2[4*i+3]=q2.w;
            wl3[4*i+0]=q3.x; wl3[4*i+1]=q3.y; wl3[4*i+2]=q3.z; wl3[4*i+3]=q3.w;
        }
#pragma unroll
        for (int e = 0; e < EMB; e++) {
            wA[e] = pack2(wl0[e], wl1[e]);
            wB[e] = pack2(wl2[e], wl3[e]);
        }
        bA = pack2(ok0 ? bl[v0] : 0.f, ok1 ? bl[v1] : 0.f);
        bB = pack2(ok2 ? bl[v2] : 0.f, ok3 ? bl[v3] : 0.f);
    }
    __syncthreads();

#pragma unroll 1
    for (int rpp = 0; rpp < E_RT / 4; rpp++) {      // 4 rows per iteration
        ull a0 = bA, a1 = bA, a2 = bA, a3 = bA;     // pair A, rows 0..3
        ull c0 = bB, c1 = bB, c2 = bB, c3 = bB;     // pair B, rows 0..3
#pragma unroll
        for (int e = 0; e < EMB; e++) {
            float4 o4 = *reinterpret_cast<const float4*>(s + e * E_RT + 4 * rpp);
            ull s0 = pack2(o4.x, o4.x);
            ull s1 = pack2(o4.y, o4.y);
            ull s2 = pack2(o4.z, o4.z);
            ull s3 = pack2(o4.w, o4.w);
            asm("fma.rn.f32x2 %0, %1, %2, %0;" : "+l"(a0) : "l"(s0), "l"(wA[e]));
            asm("fma.rn.f32x2 %0, %1, %2, %0;" : "+l"(c0) : "l"(s0), "l"(wB[e]));
            asm("fma.rn.f32x2 %0, %1, %2, %0;" : "+l"(a1) : "l"(s1), "l"(wA[e]));
            asm("fma.rn.f32x2 %0, %1, %2, %0;" : "+l"(c1) : "l"(s1), "l"(wB[e]));
            asm("fma.rn.f32x2 %0, %1, %2, %0;" : "+l"(a2) : "l"(s2), "l"(wA[e]));
            asm("fma.rn.f32x2 %0, %1, %2, %0;" : "+l"(c2) : "l"(s2), "l"(wB[e]));
            asm("fma.rn.f32x2 %0, %1, %2, %0;" : "+l"(a3) : "l"(s3), "l"(wA[e]));
            asm("fma.rn.f32x2 %0, %1, %2, %0;" : "+l"(c3) : "l"(s3), "l"(wB[e]));
        }
        size_t r = (size_t)(rbase + 4 * rpp);
        float lo, hi;
        ull accA[4] = {a0, a1, a2, a3};
        ull accB[4] = {c0, c1, c2, c3};
#pragma unroll
        for (int i = 0; i < 4; i++) {
            float* orow = out + (r + i) * VOCAB;
            unpack2(accA[i], lo, hi);
            if (ok0) __stcs(orow + v0, lo);
            if (ok1) __stcs(orow + v1, hi);
            unpack2(accB[i], lo, hi);
            if (ok2) __stcs(orow + v2, lo);
            if (ok3) __stcs(orow + v3, hi);
        }
    }
}

// ---------------- launch ----------------
extern "C" void kernel_launch(void* const* d_in, const int* in_sizes, int n_in,
                              void* d_out, int out_size) {
    const int*   x   = (const int*)  d_in[0];
    const float* emb = (const float*)d_in[1];
    const float* Wq  = (const float*)d_in[2];
    const float* bq  = (const float*)d_in[3];
    const float* Wk  = (const float*)d_in[4];
    const float* bk  = (const float*)d_in[5];
    const float* Wv  = (const float*)d_in[6];
    const float* bv  = (const float*)d_in[7];
    const float* Wl  = (const float*)d_in[8];
    const float* bl  = (const float*)d_in[9];
    float* out = (float*)d_out;

    qkv_kernel<<<NROW / 256, 256>>>(x, emb, Wq, bq, Wk, bk, Wv, bv);

    dim3 gB(MCW / 8, BS);
    scorexmax_kernel<<<gB, 256>>>();

    dim3 gD(MCW / 32, BS, NCHUNK), bD(32, 8);
    attnout_kernel<<<gD, bD>>>();

    dim3 gE((VOCAB + 511) / 512, NROW / E_RT);
    logits_kernel<<<gE, 128>>>(Wl, bl, out);
}